// round 2
// baseline (speedup 1.0000x reference)
#include <cuda_runtime.h>
#include <math_constants.h>

// Problem shape (from reference): B = 65536 rows, C = 1000 classes.
#define NCLS 1000
#define TPB  256
#define NW   (TPB / 32)
#define MAXB 65536

// Scratch for per-row losses (deterministic two-stage reduction; no fp atomics).
__device__ float g_rowloss[MAXB];

__device__ __forceinline__ float warp_max(float v) {
    #pragma unroll
    for (int o = 16; o > 0; o >>= 1) v = fmaxf(v, __shfl_xor_sync(0xffffffffu, v, o));
    return v;
}
__device__ __forceinline__ float warp_sum(float v) {
    #pragma unroll
    for (int o = 16; o > 0; o >>= 1) v += __shfl_xor_sync(0xffffffffu, v, o);
    return v;
}

__global__ __launch_bounds__(TPB)
void mvce_row_kernel(const float* __restrict__ out,
                     const float* __restrict__ tgt,
                     float* __restrict__ rowloss) {
    const int row = blockIdx.x;
    const int tid = threadIdx.x;
    const int wid = tid >> 5;
    const int lane = tid & 31;

    const float4* __restrict__ o4p =
        reinterpret_cast<const float4*>(out + (size_t)row * NCLS);
    const float4* __restrict__ t4p =
        reinterpret_cast<const float4*>(tgt + (size_t)row * NCLS);

    const bool active = (tid < NCLS / 4);   // 250 active threads, 1 float4 each

    float o[4], t[4];
    if (active) {
        float4 ov = o4p[tid];
        float4 tv = t4p[tid];
        o[0] = ov.x; o[1] = ov.y; o[2] = ov.z; o[3] = ov.w;
        t[0] = tv.x; t[1] = tv.y; t[2] = tv.z; t[3] = tv.w;
    } else {
        #pragma unroll
        for (int i = 0; i < 4; i++) { o[i] = -CUDART_INF_F; t[i] = 0.0f; }
    }

    __shared__ float sh_m[NW];
    __shared__ float sh_s[NW], sh_tn[NW], sh_an[NW];
    __shared__ float sh_l[NW], sh_np[NW];
    __shared__ float bc[4];   // broadcast: m, Sneg, Tneg, Aneg

    // ---- 1) row max ----
    float lmax = fmaxf(fmaxf(o[0], o[1]), fmaxf(o[2], o[3]));
    lmax = warp_max(lmax);
    if (lane == 0) sh_m[wid] = lmax;
    __syncthreads();
    if (wid == 0) {
        float v = (lane < NW) ? sh_m[lane] : -CUDART_INF_F;
        v = warp_max(v);
        if (lane == 0) bc[0] = v;
    }
    __syncthreads();
    const float m = bc[0];

    // ---- 2) negative-set sums: Sneg = sum e, Tneg = sum t, Aneg = sum t*o ----
    float e[4];
    float s = 0.0f, tn = 0.0f, an = 0.0f;
    #pragma unroll
    for (int i = 0; i < 4; i++) {
        e[i] = active ? __expf(o[i] - m) : 0.0f;
        if (active && t[i] <= 0.5f) {
            s  += e[i];
            tn += t[i];
            an += t[i] * o[i];
        }
    }
    s = warp_sum(s); tn = warp_sum(tn); an = warp_sum(an);
    if (lane == 0) { sh_s[wid] = s; sh_tn[wid] = tn; sh_an[wid] = an; }
    __syncthreads();
    if (wid == 0) {
        float vs  = (lane < NW) ? sh_s[lane]  : 0.0f;
        float vtn = (lane < NW) ? sh_tn[lane] : 0.0f;
        float van = (lane < NW) ? sh_an[lane] : 0.0f;
        vs = warp_sum(vs); vtn = warp_sum(vtn); van = warp_sum(van);
        if (lane == 0) { bc[1] = vs; bc[2] = vtn; bc[3] = van; }
    }
    __syncthreads();
    const float Sneg = bc[1];
    const float Tneg = bc[2];
    const float Aneg = bc[3];

    // ---- 3) positive losses ----
    float loss = 0.0f, np = 0.0f;
    if (active) {
        #pragma unroll
        for (int i = 0; i < 4; i++) {
            if (t[i] > 0.5f) {
                float lse = m + __logf(Sneg + e[i]);
                loss += (Tneg + t[i]) * lse - Aneg - t[i] * o[i];
                np += 1.0f;
            }
        }
    }
    loss = warp_sum(loss); np = warp_sum(np);
    if (lane == 0) { sh_l[wid] = loss; sh_np[wid] = np; }
    __syncthreads();
    if (tid == 0) {
        float L = 0.0f, N = 0.0f;
        #pragma unroll
        for (int w = 0; w < NW; w++) { L += sh_l[w]; N += sh_np[w]; }
        float r;
        if (N > 0.0f) {
            r = L / N;
        } else {
            r = Tneg * (m + __logf(Sneg)) - Aneg;   // no-positive fallback
        }
        rowloss[row] = r;
    }
}

__global__ __launch_bounds__(1024)
void mvce_final_reduce(const float* __restrict__ rowloss, float* __restrict__ out, int B) {
    const int tid = threadIdx.x;
    double acc = 0.0;
    for (int i = tid; i < B; i += 1024) acc += (double)rowloss[i];
    // warp reduce (double)
    #pragma unroll
    for (int o = 16; o > 0; o >>= 1) acc += __shfl_xor_sync(0xffffffffu, acc, o);
    __shared__ double sh[32];
    if ((tid & 31) == 0) sh[tid >> 5] = acc;
    __syncthreads();
    if (tid < 32) {
        double v = (tid < 32) ? sh[tid] : 0.0;
        #pragma unroll
        for (int o = 16; o > 0; o >>= 1) v += __shfl_xor_sync(0xffffffffu, v, o);
        if (tid == 0) out[0] = (float)(v / (double)B);
    }
}

extern "C" void kernel_launch(void* const* d_in, const int* in_sizes, int n_in,
                              void* d_out, int out_size) {
    const float* output = (const float*)d_in[0];
    const float* target = (const float*)d_in[1];
    float* out = (float*)d_out;

    const int B = in_sizes[0] / NCLS;

    float* rowloss;
    cudaGetSymbolAddress((void**)&rowloss, g_rowloss);

    mvce_row_kernel<<<B, TPB>>>(output, target, rowloss);
    mvce_final_reduce<<<1, 1024>>>(rowloss, out, B);
}